// round 7
// baseline (speedup 1.0000x reference)
#include <cuda_runtime.h>
#include <cstdint>

#define T_STEPS 2048
#define BATCH   1024
#define INPUT   4
#define HID     10
#define OUTF    4
#define CHUNK   16          // timesteps staged per cp.async chunk
#define BPB     8           // batches per block (2 warps * 2 halves * 2 packed)
#define THREADS 64          // 2 warps -> 128 blocks, 2 SMSPs busy per SM

typedef unsigned long long u64;

// ---- Blackwell packed f32x2 helpers ----
__device__ __forceinline__ u64 pk2(float lo, float hi) {
    u64 r; asm("mov.b64 %0, {%1,%2};" : "=l"(r) : "f"(lo), "f"(hi)); return r;
}
__device__ __forceinline__ void up2(u64 v, float& lo, float& hi) {
    asm("mov.b64 {%0,%1}, %2;" : "=f"(lo), "=f"(hi) : "l"(v));
}
__device__ __forceinline__ u64 ffma2(u64 a, u64 b, u64 c) {
    u64 d; asm("fma.rn.f32x2 %0, %1, %2, %3;" : "=l"(d) : "l"(a), "l"(b), "l"(c)); return d;
}
__device__ __forceinline__ u64 fadd2(u64 a, u64 b) {
    u64 d; asm("add.rn.f32x2 %0, %1, %2;" : "=l"(d) : "l"(a), "l"(b)); return d;
}
__device__ __forceinline__ u64 fmul2(u64 a, u64 b) {
    u64 d; asm("mul.rn.f32x2 %0, %1, %2;" : "=l"(d) : "l"(a), "l"(b)); return d;
}

// HW tanh (MUFU)
__device__ __forceinline__ float htanh(float x) {
    float y; asm("tanh.approx.f32 %0, %1;" : "=f"(y) : "f"(x)); return y;
}

__device__ __forceinline__ void cp_async16(void* dst, const void* src) {
    unsigned d = (unsigned)__cvta_generic_to_shared(dst);
    asm volatile("cp.async.ca.shared.global [%0], [%1], 16;\n" :: "r"(d), "l"(src));
}
__device__ __forceinline__ void cp_commit() {
    asm volatile("cp.async.commit_group;\n" ::: "memory");
}
__device__ __forceinline__ void cp_wait1() {
    asm volatile("cp.async.wait_group 1;\n" ::: "memory");
}

__global__ void __launch_bounds__(THREADS, 1)
lstm_persistent_kernel(const float* __restrict__ x,
                       const float* __restrict__ h0,
                       const float* __restrict__ c0,
                       const float* __restrict__ W_ih,
                       const float* __restrict__ W_hh,
                       const float* __restrict__ b_ih,
                       const float* __restrict__ b_hh,
                       const float* __restrict__ W_fc,
                       const float* __restrict__ b_fc,
                       float* __restrict__ out,
                       int write_state)
{
    __shared__ float4 sx[2][CHUNK][BPB];

    const int tid  = threadIdx.x;
    const int warp = tid >> 5;
    const int lane = tid & 31;
    const int half = lane >> 4;      // which batch-pair within the warp
    const int jj   = lane & 15;      // lane id within 16-lane group
    const int j    = (jj < HID) ? jj : (HID - 1);  // clamped hidden index

    const int gbase = blockIdx.x * BPB;
    const int p     = warp * 2 + half;     // batch-pair index within block 0..3
    const int b0    = gbase + 2 * p;       // two batches handled by this lane group
    const int b1    = b0 + 1;

    // ---- per-lane weights, duplicated {w,w} for batch-pair FFMA2 ----
    // Gates i(0), f(1), o(3) prescaled by 0.5 so sigmoid = 0.5*tanh(acc)+0.5
    u64 wih[4][INPUT], whh[4][HID], bias2[4];
#pragma unroll
    for (int g = 0; g < 4; g++) {
        const float sc = (g == 2) ? 1.0f : 0.5f;
        const int row = g * HID + j;
#pragma unroll
        for (int k = 0; k < INPUT; k++) {
            const float w = W_ih[row * INPUT + k] * sc;
            wih[g][k] = pk2(w, w);
        }
#pragma unroll
        for (int k = 0; k < HID; k++) {
            const float w = W_hh[row * HID + k] * sc;
            whh[g][k] = pk2(w, w);
        }
        const float b = (b_ih[row] + b_hh[row]) * sc;
        bias2[g] = pk2(b, b);
    }
    const int jo = (jj < OUTF) ? jj : 0;
    const float bfc = b_fc[jo];
    const u64 bfc2 = pk2(bfc, bfc);
    u64 wfcd[HID];
#pragma unroll
    for (int k = 0; k < HID; k++) {
        const float w = W_fc[jo * HID + k];
        wfcd[k] = pk2(w, w);
    }

    // ---- state: h and c packed {batch b0, batch b1} ----
    u64 hd[HID];
#pragma unroll
    for (int k = 0; k < HID; k++)
        hd[k] = pk2(h0[b0 * HID + k], h0[b1 * HID + k]);
    u64 c2 = pk2(c0[b0 * HID + j], c0[b1 * HID + j]);

    const float4* x4 = reinterpret_cast<const float4*>(x);

    // prefetch chunk 0 (CHUNK*BPB = 128 float4, 64 threads -> 2 each)
#pragma unroll
    for (int e = tid; e < CHUNK * BPB; e += THREADS)
        cp_async16(&sx[0][e >> 3][e & 7], x4 + (size_t)(e >> 3) * BATCH + gbase + (e & 7));
    cp_commit();

    const int NCH = T_STEPS / CHUNK;   // 128
    for (int ch = 0; ch < NCH; ch++) {
        if (ch + 1 < NCH) {
#pragma unroll
            for (int e = tid; e < CHUNK * BPB; e += THREADS)
                cp_async16(&sx[(ch + 1) & 1][e >> 3][e & 7],
                           x4 + (size_t)((ch + 1) * CHUNK + (e >> 3)) * BATCH + gbase + (e & 7));
        }
        cp_commit();
        cp_wait1();          // chunk `ch` resident
        __syncthreads();

        const int buf = ch & 1;
#pragma unroll 2
        for (int s = 0; s < CHUNK; s++) {
            const float4 xv0 = sx[buf][s][2 * p];
            const float4 xv1 = sx[buf][s][2 * p + 1];
            u64 xd[INPUT];
            xd[0] = pk2(xv0.x, xv1.x);
            xd[1] = pk2(xv0.y, xv1.y);
            xd[2] = pk2(xv0.z, xv1.z);
            xd[3] = pk2(xv0.w, xv1.w);

            // 4 gate dots (each f32x2 over the batch pair), 2 accumulators each
            u64 acc[4];
#pragma unroll
            for (int g = 0; g < 4; g++) {
                u64 a = ffma2(xd[0], wih[g][0], bias2[g]);
                u64 b = fmul2(xd[1], wih[g][1]);
                a = ffma2(xd[2], wih[g][2], a);
                b = ffma2(xd[3], wih[g][3], b);
#pragma unroll
                for (int k = 0; k < HID; k += 2) {
                    a = ffma2(hd[k],     whh[g][k],     a);
                    b = ffma2(hd[k + 1], whh[g][k + 1], b);
                }
                acc[g] = fadd2(a, b);
            }

            float zi0, zi1, zf0, zf1, zg0, zg1, zo0, zo1;
            up2(acc[0], zi0, zi1);
            up2(acc[1], zf0, zf1);
            up2(acc[2], zg0, zg1);
            up2(acc[3], zo0, zo1);

            // all 8 MUFUs independent -> pipeline through the SFU
            const float ti0 = htanh(zi0), ti1 = htanh(zi1);
            const float tf0 = htanh(zf0), tf1 = htanh(zf1);
            const float tg0 = htanh(zg0), tg1 = htanh(zg1);
            const float to0 = htanh(zo0), to1 = htanh(zo1);

            const float ig0 = fmaf(0.5f, ti0, 0.5f), ig1 = fmaf(0.5f, ti1, 0.5f);
            const float fg0 = fmaf(0.5f, tf0, 0.5f), fg1 = fmaf(0.5f, tf1, 0.5f);
            const float og0 = fmaf(0.5f, to0, 0.5f), og1 = fmaf(0.5f, to1, 0.5f);

            // packed c update: c = f*c + i*g
            const u64 ig2 = fmul2(pk2(ig0, ig1), pk2(tg0, tg1));
            c2 = ffma2(pk2(fg0, fg1), c2, ig2);

            float cc0, cc1;
            up2(c2, cc0, cc1);
            const float hn0 = og0 * htanh(cc0);
            const float hn1 = og1 * htanh(cc1);

            // broadcast both batches' new h across the 16-lane group
#pragma unroll
            for (int k = 0; k < HID; k++) {
                const float lo = __shfl_sync(0xffffffffu, hn0, k, 16);
                const float hi = __shfl_sync(0xffffffffu, hn1, k, 16);
                hd[k] = pk2(lo, hi);
            }

            if (jj < OUTF) {
                u64 fa = ffma2(hd[0], wfcd[0], bfc2);
                u64 fb = fmul2(hd[1], wfcd[1]);
#pragma unroll
                for (int k = 2; k < HID; k += 2) {
                    fa = ffma2(hd[k],     wfcd[k],     fa);
                    fb = ffma2(hd[k + 1], wfcd[k + 1], fb);
                }
                float d0, d1;
                up2(fadd2(fa, fb), d0, d1);
                const int t = ch * CHUNK + s;
                out[((size_t)t * BATCH + b0) * OUTF + jj] = d0;
                out[((size_t)t * BATCH + b1) * OUTF + jj] = d1;
            }
        }
        __syncthreads();   // everyone done with buf before it gets overwritten
    }

    // ---- final states (hT, cT) appended after `out` in the flattened pytree ----
    if (write_state && jj < HID) {
        float h0v, h1v, c0v, c1v;
        up2(hd[jj], h0v, h1v);
        up2(c2, c0v, c1v);
        const size_t off = (size_t)T_STEPS * BATCH * OUTF;
        out[off + (size_t)b0 * HID + jj] = h0v;
        out[off + (size_t)b1 * HID + jj] = h1v;
        out[off + (size_t)BATCH * HID + (size_t)b0 * HID + jj] = c0v;
        out[off + (size_t)BATCH * HID + (size_t)b1 * HID + jj] = c1v;
    }
}

extern "C" void kernel_launch(void* const* d_in, const int* in_sizes, int n_in,
                              void* d_out, int out_size) {
    const float* x    = (const float*)d_in[0];
    const float* h0   = (const float*)d_in[1];
    const float* c0   = (const float*)d_in[2];
    const float* W_ih = (const float*)d_in[3];
    const float* W_hh = (const float*)d_in[4];
    const float* b_ih = (const float*)d_in[5];
    const float* b_hh = (const float*)d_in[6];
    const float* W_fc = (const float*)d_in[7];
    const float* b_fc = (const float*)d_in[8];
    float* out = (float*)d_out;

    const long long need_state = (long long)T_STEPS * BATCH * OUTF + 2LL * BATCH * HID;
    const int write_state = (out_size >= need_state) ? 1 : 0;

    lstm_persistent_kernel<<<BATCH / BPB, THREADS>>>(
        x, h0, c0, W_ih, W_hh, b_ih, b_hh, W_fc, b_fc, out, write_state);
}

// round 9
// speedup vs baseline: 2.4624x; 2.4624x over previous
#include <cuda_runtime.h>
#include <cstdint>

#define T_STEPS 2048
#define BATCH   1024
#define INPUT   4
#define HID     10
#define OUTF    4
#define CHUNK   16          // timesteps staged per cp.async chunk
#define BPB     8           // batches per block = warps per block (1 batch/warp)
#define THREADS 256         // 8 warps -> 128 blocks, 2 warps per SMSP

typedef unsigned long long u64;

// 84MB scratch for h history (module-static: no runtime allocation)
__device__ float g_hhist[(size_t)T_STEPS * BATCH * HID];

// ---- Blackwell packed f32x2 helpers ----
__device__ __forceinline__ u64 pk2(float lo, float hi) {
    u64 r; asm("mov.b64 %0, {%1,%2};" : "=l"(r) : "f"(lo), "f"(hi)); return r;
}
__device__ __forceinline__ void up2(u64 v, float& lo, float& hi) {
    asm("mov.b64 {%0,%1}, %2;" : "=f"(lo), "=f"(hi) : "l"(v));
}
__device__ __forceinline__ u64 ffma2(u64 a, u64 b, u64 c) {
    u64 d; asm("fma.rn.f32x2 %0, %1, %2, %3;" : "=l"(d) : "l"(a), "l"(b), "l"(c)); return d;
}
__device__ __forceinline__ u64 fadd2(u64 a, u64 b) {
    u64 d; asm("add.rn.f32x2 %0, %1, %2;" : "=l"(d) : "l"(a), "l"(b)); return d;
}
__device__ __forceinline__ u64 fmul2(u64 a, u64 b) {
    u64 d; asm("mul.rn.f32x2 %0, %1, %2;" : "=l"(d) : "l"(a), "l"(b)); return d;
}

// HW tanh (MUFU)
__device__ __forceinline__ float htanh(float x) {
    float y; asm("tanh.approx.f32 %0, %1;" : "=f"(y) : "f"(x)); return y;
}

__device__ __forceinline__ void cp_async16(void* dst, const void* src) {
    unsigned d = (unsigned)__cvta_generic_to_shared(dst);
    asm volatile("cp.async.ca.shared.global [%0], [%1], 16;\n" :: "r"(d), "l"(src));
}
__device__ __forceinline__ void cp_commit() {
    asm volatile("cp.async.commit_group;\n" ::: "memory");
}
__device__ __forceinline__ void cp_wait1() {
    asm volatile("cp.async.wait_group 1;\n" ::: "memory");
}

// ============================================================================
// Phase 1: recurrence. One batch per warp. Lanes 0-9: (i,f) rows packed in
// f32x2; lanes 16-25: (g,o) rows. Gate halves recombined with 2 shfl.bfly.
// FC deferred: h written to g_hhist each step.
// ============================================================================
__global__ void __launch_bounds__(THREADS, 1)
lstm_recurrence_kernel(const float* __restrict__ x,
                       const float* __restrict__ h0,
                       const float* __restrict__ c0,
                       const float* __restrict__ W_ih,
                       const float* __restrict__ W_hh,
                       const float* __restrict__ b_ih,
                       const float* __restrict__ b_hh,
                       float* __restrict__ out,
                       int write_state)
{
    __shared__ float4 sx[2][CHUNK][BPB];

    const int tid  = threadIdx.x;
    const int warp = tid >> 5;
    const int lane = tid & 31;
    const int role = (lane >> 4) & 1;          // 0: (i,f) rows, 1: (g,o) rows
    const int jj   = lane & 15;
    const int j    = (jj < HID) ? jj : (HID - 1);

    const int batch = blockIdx.x * BPB + warp;

    // rows for this lane: r_lo = role*2*HID + j (i or g), r_hi = r_lo + HID (f or o)
    const int r_lo = role * 2 * HID + j;
    const int r_hi = r_lo + HID;
    // prescale: sigmoid gates (i,f,o) by 0.5 so sigmoid = 0.5*tanh(acc)+0.5 ; g by 1
    const float s_lo = role ? 1.0f : 0.5f;
    const float s_hi = 0.5f;

    u64 wih[INPUT], whh[HID], bias2;
#pragma unroll
    for (int k = 0; k < INPUT; k++)
        wih[k] = pk2(W_ih[r_lo * INPUT + k] * s_lo, W_ih[r_hi * INPUT + k] * s_hi);
#pragma unroll
    for (int k = 0; k < HID; k++)
        whh[k] = pk2(W_hh[r_lo * HID + k] * s_lo, W_hh[r_hi * HID + k] * s_hi);
    bias2 = pk2((b_ih[r_lo] + b_hh[r_lo]) * s_lo, (b_ih[r_hi] + b_hh[r_hi]) * s_hi);

    // state: h duplicated {h,h}; c scalar (meaningful on lanes 0-9)
    u64 hd[HID];
#pragma unroll
    for (int k = 0; k < HID; k++) {
        const float hv = h0[batch * HID + k];
        hd[k] = pk2(hv, hv);
    }
    float c = c0[batch * HID + j];
    float hlast = 0.0f;

    const float4* x4 = reinterpret_cast<const float4*>(x);

    // prefetch chunk 0 (CHUNK*BPB = 128 float4)
    if (tid < CHUNK * BPB)
        cp_async16(&sx[0][tid >> 3][tid & 7],
                   x4 + (size_t)(tid >> 3) * BATCH + blockIdx.x * BPB + (tid & 7));
    cp_commit();

    const int NCH = T_STEPS / CHUNK;   // 128
    for (int ch = 0; ch < NCH; ch++) {
        if (ch + 1 < NCH && tid < CHUNK * BPB) {
            cp_async16(&sx[(ch + 1) & 1][tid >> 3][tid & 7],
                       x4 + (size_t)((ch + 1) * CHUNK + (tid >> 3)) * BATCH
                          + blockIdx.x * BPB + (tid & 7));
        }
        cp_commit();
        cp_wait1();
        __syncthreads();

        const int buf = ch & 1;
#pragma unroll 2
        for (int s = 0; s < CHUNK; s++) {
            const float4 xv = sx[buf][s][warp];   // warp-uniform broadcast
            const u64 xd0 = pk2(xv.x, xv.x);
            const u64 xd1 = pk2(xv.y, xv.y);
            const u64 xd2 = pk2(xv.z, xv.z);
            const u64 xd3 = pk2(xv.w, xv.w);

            // one packed gate-pair dot per lane: 14 FFMA2, two accumulators
            u64 a = ffma2(xd0, wih[0], bias2);
            u64 b = fmul2(xd1, wih[1]);
            a = ffma2(xd2, wih[2], a);
            b = ffma2(xd3, wih[3], b);
#pragma unroll
            for (int k = 0; k < HID; k += 2) {
                a = ffma2(hd[k],     whh[k],     a);
                b = ffma2(hd[k + 1], whh[k + 1], b);
            }
            float za, zb;
            up2(fadd2(a, b), za, zb);

            const float ta = htanh(za);    // lanes0-9: tanh(i/2) ; lanes16-25: tanh(g)
            const float tb = htanh(zb);    // lanes0-9: tanh(f/2) ; lanes16-25: tanh(o/2)

            // exchange gate halves across the 16-lane boundary
            const float tra = __shfl_xor_sync(0xffffffffu, ta, 16);  // on role0: tanh(g)
            const float trb = __shfl_xor_sync(0xffffffffu, tb, 16);  // on role0: tanh(o/2)

            // c/h update (meaningful on lanes 0-9; other lanes compute garbage)
            const float ig = fmaf(0.5f, ta, 0.5f);
            const float fg = fmaf(0.5f, tb, 0.5f);
            const float og = fmaf(0.5f, trb, 0.5f);
            c = fmaf(fg, c, ig * tra);
            const float hn = og * htanh(c);
            hlast = hn;

            // broadcast new h (sources: lanes 0-9) and re-duplicate
#pragma unroll
            for (int k = 0; k < HID; k++) {
                const float hk = __shfl_sync(0xffffffffu, hn, k, 32);
                hd[k] = pk2(hk, hk);
            }

            // record h for the deferred FC pass
            if (lane < HID) {
                const int t = ch * CHUNK + s;
                g_hhist[((size_t)t * BATCH + batch) * HID + lane] = hn;
            }
        }
        __syncthreads();
    }

    // final states (hT, cT) appended after `out` in the flattened pytree
    if (write_state && lane < HID) {
        const size_t off = (size_t)T_STEPS * BATCH * OUTF;
        out[off + (size_t)batch * HID + lane] = hlast;
        out[off + (size_t)BATCH * HID + (size_t)batch * HID + lane] = c;
    }
}

// ============================================================================
// Phase 2: out[t*B+b, :] = h[t,b,:] @ W_fc^T + b_fc   (embarrassingly parallel)
// ============================================================================
__global__ void __launch_bounds__(256)
lstm_fc_kernel(const float* __restrict__ W_fc,
               const float* __restrict__ b_fc,
               float* __restrict__ out)
{
    __shared__ float wf[OUTF * HID];
    __shared__ float bf[OUTF];
    if (threadIdx.x < OUTF * HID) wf[threadIdx.x] = W_fc[threadIdx.x];
    if (threadIdx.x < OUTF)       bf[threadIdx.x] = b_fc[threadIdx.x];
    __syncthreads();

    const size_t idx = (size_t)blockIdx.x * blockDim.x + threadIdx.x;  // (t,b) pair
    if (idx >= (size_t)T_STEPS * BATCH) return;

    const float* h = &g_hhist[idx * HID];
    float hv[HID];
    const float2* h2 = reinterpret_cast<const float2*>(h);   // 40B rows -> 8B aligned
#pragma unroll
    for (int k = 0; k < HID / 2; k++) {
        const float2 v = h2[k];
        hv[2 * k] = v.x; hv[2 * k + 1] = v.y;
    }

    float4 r;
    float* rp = reinterpret_cast<float*>(&r);
#pragma unroll
    for (int o = 0; o < OUTF; o++) {
        float acc0 = bf[o], acc1 = 0.0f;
#pragma unroll
        for (int k = 0; k < HID; k += 2) {
            acc0 = fmaf(hv[k],     wf[o * HID + k],     acc0);
            acc1 = fmaf(hv[k + 1], wf[o * HID + k + 1], acc1);
        }
        rp[o] = acc0 + acc1;
    }
    reinterpret_cast<float4*>(out)[idx] = r;
}

extern "C" void kernel_launch(void* const* d_in, const int* in_sizes, int n_in,
                              void* d_out, int out_size) {
    const float* x    = (const float*)d_in[0];
    const float* h0   = (const float*)d_in[1];
    const float* c0   = (const float*)d_in[2];
    const float* W_ih = (const float*)d_in[3];
    const float* W_hh = (const float*)d_in[4];
    const float* b_ih = (const float*)d_in[5];
    const float* b_hh = (const float*)d_in[6];
    const float* W_fc = (const float*)d_in[7];
    const float* b_fc = (const float*)d_in[8];
    float* out = (float*)d_out;

    const long long need_state = (long long)T_STEPS * BATCH * OUTF + 2LL * BATCH * HID;
    const int write_state = (out_size >= need_state) ? 1 : 0;

    lstm_recurrence_kernel<<<BATCH / BPB, THREADS>>>(
        x, h0, c0, W_ih, W_hh, b_ih, b_hh, out, write_state);

    const long long nrows = (long long)T_STEPS * BATCH;
    lstm_fc_kernel<<<(int)((nrows + 255) / 256), 256>>>(W_fc, b_fc, out);
}

// round 11
// speedup vs baseline: 2.6312x; 1.0685x over previous
#include <cuda_runtime.h>
#include <cstdint>

#define T_STEPS 2048
#define BATCH   1024
#define INPUT   4
#define HID     10
#define OUTF    4
#define CHUNK   16          // timesteps staged per warp per cp.async chunk
#define BPB     8           // batches per block = warps per block (1 batch/warp)
#define THREADS 256         // 8 warps -> 128 blocks, 2 warps per SMSP

typedef unsigned long long u64;

// 84MB scratch for h history (module-static: no runtime allocation)
__device__ float g_hhist[(size_t)T_STEPS * BATCH * HID];

// ---- Blackwell packed f32x2 helpers ----
__device__ __forceinline__ u64 pk2(float lo, float hi) {
    u64 r; asm("mov.b64 %0, {%1,%2};" : "=l"(r) : "f"(lo), "f"(hi)); return r;
}
__device__ __forceinline__ void up2(u64 v, float& lo, float& hi) {
    asm("mov.b64 {%0,%1}, %2;" : "=f"(lo), "=f"(hi) : "l"(v));
}
__device__ __forceinline__ u64 ffma2(u64 a, u64 b, u64 c) {
    u64 d; asm("fma.rn.f32x2 %0, %1, %2, %3;" : "=l"(d) : "l"(a), "l"(b), "l"(c)); return d;
}
__device__ __forceinline__ u64 fadd2(u64 a, u64 b) {
    u64 d; asm("add.rn.f32x2 %0, %1, %2;" : "=l"(d) : "l"(a), "l"(b)); return d;
}
__device__ __forceinline__ u64 fmul2(u64 a, u64 b) {
    u64 d; asm("mul.rn.f32x2 %0, %1, %2;" : "=l"(d) : "l"(a), "l"(b)); return d;
}

// HW tanh (MUFU)
__device__ __forceinline__ float htanh(float x) {
    float y; asm("tanh.approx.f32 %0, %1;" : "=f"(y) : "f"(x)); return y;
}

__device__ __forceinline__ void cp_async16(void* dst, const void* src) {
    unsigned d = (unsigned)__cvta_generic_to_shared(dst);
    asm volatile("cp.async.ca.shared.global [%0], [%1], 16;\n" :: "r"(d), "l"(src));
}
__device__ __forceinline__ void cp_commit() {
    asm volatile("cp.async.commit_group;\n" ::: "memory");
}
__device__ __forceinline__ void cp_wait1() {
    asm volatile("cp.async.wait_group 1;\n" ::: "memory");
}

// ============================================================================
// Phase 1: recurrence. One batch per warp, fully warp-autonomous (no block
// sync in the loop -> warps de-phase and interleave in the SMSP).
// Lanes 0-9: (i,f) rows packed f32x2; lanes 16-25: (g,o) rows.
// FC deferred to phase 2 via g_hhist.
// ============================================================================
__global__ void __launch_bounds__(THREADS, 1)
lstm_recurrence_kernel(const float* __restrict__ x,
                       const float* __restrict__ h0,
                       const float* __restrict__ c0,
                       const float* __restrict__ W_ih,
                       const float* __restrict__ W_hh,
                       const float* __restrict__ b_ih,
                       const float* __restrict__ b_hh,
                       float* __restrict__ out,
                       int write_state)
{
    // per-warp private double-buffered x stage: 8 warps * 2 bufs * 16 steps * 16B
    __shared__ float4 sx[BPB][2][CHUNK];

    const int tid  = threadIdx.x;
    const int warp = tid >> 5;
    const int lane = tid & 31;
    const int role = (lane >> 4) & 1;          // 0: (i,f) rows, 1: (g,o) rows
    const int jj   = lane & 15;
    const int j    = (jj < HID) ? jj : (HID - 1);

    const int batch = blockIdx.x * BPB + warp;

    // rows: r_lo = role*2*HID + j (i or g), r_hi = r_lo + HID (f or o)
    const int r_lo = role * 2 * HID + j;
    const int r_hi = r_lo + HID;
    // prescale sigmoid gates (i,f,o) by 0.5 so sigmoid = 0.5*tanh(acc)+0.5
    const float s_lo = role ? 1.0f : 0.5f;
    const float s_hi = 0.5f;

    u64 wih[INPUT], whh[HID], bias2;
#pragma unroll
    for (int k = 0; k < INPUT; k++)
        wih[k] = pk2(W_ih[r_lo * INPUT + k] * s_lo, W_ih[r_hi * INPUT + k] * s_hi);
#pragma unroll
    for (int k = 0; k < HID; k++)
        whh[k] = pk2(W_hh[r_lo * HID + k] * s_lo, W_hh[r_hi * HID + k] * s_hi);
    bias2 = pk2((b_ih[r_lo] + b_hh[r_lo]) * s_lo, (b_ih[r_hi] + b_hh[r_hi]) * s_hi);

    // state: h duplicated {h,h}; c scalar (meaningful on lanes 0-9)
    u64 hd[HID];
#pragma unroll
    for (int k = 0; k < HID; k++) {
        const float hv = h0[batch * HID + k];
        hd[k] = pk2(hv, hv);
    }
    float c = c0[batch * HID + j];
    float hlast = 0.0f;

    const float4* x4 = reinterpret_cast<const float4*>(x);

    // prefetch chunk 0: lanes 0-15 fetch one timestep each (this warp's batch)
    if (lane < CHUNK)
        cp_async16(&sx[warp][0][lane], x4 + (size_t)lane * BATCH + batch);
    cp_commit();

    const int NCH = T_STEPS / CHUNK;   // 128
    for (int ch = 0; ch < NCH; ch++) {
        if (ch + 1 < NCH && lane < CHUNK) {
            cp_async16(&sx[warp][(ch + 1) & 1][lane],
                       x4 + (size_t)((ch + 1) * CHUNK + lane) * BATCH + batch);
        }
        cp_commit();
        cp_wait1();          // this warp's chunk `ch` resident
        __syncwarp();        // make async-copied data visible warp-wide

        const int buf = ch & 1;
#pragma unroll 2
        for (int s = 0; s < CHUNK; s++) {
            const float4 xv = sx[warp][buf][s];   // warp-uniform broadcast
            const u64 xd0 = pk2(xv.x, xv.x);
            const u64 xd1 = pk2(xv.y, xv.y);
            const u64 xd2 = pk2(xv.z, xv.z);
            const u64 xd3 = pk2(xv.w, xv.w);

            // x-part: independent of h broadcast -> computes during shfl wait
            u64 xc = ffma2(xd0, wih[0], bias2);
            u64 xc2 = fmul2(xd1, wih[1]);
            xc  = ffma2(xd2, wih[2], xc);
            xc2 = ffma2(xd3, wih[3], xc2);

            // h-part: 4 short accumulator chains (depth 3,3,2,2) + tree combine
            u64 a = ffma2(hd[0], whh[0], xc);
            u64 b = ffma2(hd[1], whh[1], xc2);
            u64 cc = fmul2(hd[2], whh[2]);
            u64 dd = fmul2(hd[3], whh[3]);
            a  = ffma2(hd[4], whh[4], a);
            b  = ffma2(hd[5], whh[5], b);
            cc = ffma2(hd[6], whh[6], cc);
            dd = ffma2(hd[7], whh[7], dd);
            a  = ffma2(hd[8], whh[8], a);
            b  = ffma2(hd[9], whh[9], b);
            float za, zb;
            up2(fadd2(fadd2(a, cc), fadd2(b, dd)), za, zb);

            const float ta = htanh(za);    // role0: tanh(i/2) ; role1: tanh(g)
            const float tb = htanh(zb);    // role0: tanh(f/2) ; role1: tanh(o/2)

            // exchange gate halves across the 16-lane boundary
            const float tra = __shfl_xor_sync(0xffffffffu, ta, 16);  // role0: tanh(g)
            const float trb = __shfl_xor_sync(0xffffffffu, tb, 16);  // role0: tanh(o/2)

            // c/h update (meaningful on lanes 0-9)
            const float ig = fmaf(0.5f, ta, 0.5f);
            const float fg = fmaf(0.5f, tb, 0.5f);
            const float og = fmaf(0.5f, trb, 0.5f);
            c = fmaf(fg, c, ig * tra);
            const float hn = og * htanh(c);
            hlast = hn;

            // broadcast new h (sources: lanes 0-9) and re-duplicate
#pragma unroll
            for (int k = 0; k < HID; k++) {
                const float hk = __shfl_sync(0xffffffffu, hn, k, 32);
                hd[k] = pk2(hk, hk);
            }

            // record h for the deferred FC pass
            if (lane < HID) {
                const int t = ch * CHUNK + s;
                g_hhist[((size_t)t * BATCH + batch) * HID + lane] = hn;
            }
        }
    }

    // final states (hT, cT) appended after `out` in the flattened pytree
    if (write_state && lane < HID) {
        const size_t off = (size_t)T_STEPS * BATCH * OUTF;
        out[off + (size_t)batch * HID + lane] = hlast;
        out[off + (size_t)BATCH * HID + (size_t)batch * HID + lane] = c;
    }
}

// ============================================================================
// Phase 2: out[t*B+b, :] = h[t,b,:] @ W_fc^T + b_fc   (embarrassingly parallel)
// ============================================================================
__global__ void __launch_bounds__(256)
lstm_fc_kernel(const float* __restrict__ W_fc,
               const float* __restrict__ b_fc,
               float* __restrict__ out)
{
    __shared__ float wf[OUTF * HID];
    __shared__ float bf[OUTF];
    if (threadIdx.x < OUTF * HID) wf[threadIdx.x] = W_fc[threadIdx.x];
    if (threadIdx.x < OUTF)       bf[threadIdx.x] = b_fc[threadIdx.x];
    __syncthreads();

    const size_t idx = (size_t)blockIdx.x * blockDim.x + threadIdx.x;  // (t,b) pair
    if (idx >= (size_t)T_STEPS * BATCH) return;

    const float* h = &g_hhist[idx * HID];
    float hv[HID];
    const float2* h2 = reinterpret_cast<const float2*>(h);   // 40B rows -> 8B aligned
#pragma unroll
    for (int k = 0; k < HID / 2; k++) {
        const float2 v = h2[k];
        hv[2 * k] = v.x; hv[2 * k + 1] = v.y;
    }

    float4 r;
    float* rp = reinterpret_cast<float*>(&r);
#pragma unroll
    for (int o = 0; o < OUTF; o++) {
        float acc0 = bf[o], acc1 = 0.0f;
#pragma unroll
        for (int k = 0; k < HID; k += 2) {
            acc0 = fmaf(hv[k],     wf[o * HID + k],     acc0);
            acc1 = fmaf(hv[k + 1], wf[o * HID + k + 1], acc1);
        }
        rp[o] = acc0 + acc1;
    }
    reinterpret_cast<float4*>(out)[idx] = r;
}

extern "C" void kernel_launch(void* const* d_in, const int* in_sizes, int n_in,
                              void* d_out, int out_size) {
    const float* x    = (const float*)d_in[0];
    const float* h0   = (const float*)d_in[1];
    const float* c0   = (const float*)d_in[2];
    const float* W_ih = (const float*)d_in[3];
    const float* W_hh = (const float*)d_in[4];
    const float* b_ih = (const float*)d_in[5];
    const float* b_hh = (const float*)d_in[6];
    const float* W_fc = (const float*)d_in[7];
    const float* b_fc = (const float*)d_in[8];
    float* out = (float*)d_out;

    const long long need_state = (long long)T_STEPS * BATCH * OUTF + 2LL * BATCH * HID;
    const int write_state = (out_size >= need_state) ? 1 : 0;

    lstm_recurrence_kernel<<<BATCH / BPB, THREADS>>>(
        x, h0, c0, W_ih, W_hh, b_ih, b_hh, out, write_state);

    const long long nrows = (long long)T_STEPS * BATCH;
    lstm_fc_kernel<<<(int)((nrows + 255) / 256), 256>>>(W_fc, b_fc, out);
}